// round 17
// baseline (speedup 1.0000x reference)
#include <cuda_runtime.h>
#include <cuda_fp16.h>
#include <cstdint>

// FullAttention via mma.sync m16n8k16 fp16 (Q,K,P,V fp16; f32 accumulate).
// R16: attn restructured to 4 warps x 32 query rows with RESIDENT B-fragments
// (bhAll/vfAll held in registers, loaded once per tile -> LDSM halved), tile
// loads via cp.async 16B (no RF transit), 3 blocks/SM. Prep unchanged from R15.

#define LSEQ 2048
#define DH 32
#define NHEAD 8
#define NB 4
#define NH_TOT (NB * NHEAD)
#define TKK 64
#define TQ 128
#define PK 40    // Ks pitch (fp16): 80B rows, ldmatrix conflict-free
#define PVV 72   // Vh pitch: 144B rows, conflict-free

__device__ int    g_cidx[NB][LSEQ];
__device__ int    g_cnt[NB];
__device__ float  g_vmean[NH_TOT * DH];
__device__ __half g_Kc[NH_TOT][LSEQ][DH];   // compacted keys, key-major
__device__ __half g_Vc[NH_TOT][DH][LSEQ];   // compacted values, d-major

static __device__ __forceinline__ float ex2f(float x) {
    float y; asm("ex2.approx.ftz.f32 %0, %1;" : "=f"(y) : "f"(x)); return y;
}
static __device__ __forceinline__ uint32_t smem_u32(const void* p) {
    uint32_t a; asm("{ .reg .u64 t; cvta.to.shared.u64 t, %1; cvt.u32.u64 %0, t; }" : "=r"(a) : "l"(p));
    return a;
}
static __device__ __forceinline__ uint32_t packh(float e0, float e1) {
    uint32_t r; asm("cvt.rn.f16x2.f32 %0, %1, %2;" : "=r"(r) : "f"(e1), "f"(e0)); return r;
}
static __device__ __forceinline__ void mma16816(float* c, const uint32_t* a, const uint32_t* b) {
    asm volatile("mma.sync.aligned.m16n8k16.row.col.f32.f16.f16.f32 "
        "{%0,%1,%2,%3}, {%4,%5,%6,%7}, {%8,%9}, {%0,%1,%2,%3};"
        : "+f"(c[0]), "+f"(c[1]), "+f"(c[2]), "+f"(c[3])
        : "r"(a[0]), "r"(a[1]), "r"(a[2]), "r"(a[3]), "r"(b[0]), "r"(b[1]));
}
static __device__ __forceinline__ void ldmx4(uint32_t* d, uint32_t addr) {
    asm volatile("ldmatrix.sync.aligned.m8n8.x4.shared.b16 {%0,%1,%2,%3}, [%4];"
        : "=r"(d[0]), "=r"(d[1]), "=r"(d[2]), "=r"(d[3]) : "r"(addr));
}
static __device__ __forceinline__ void cpasync16(uint32_t dst, const void* src) {
    asm volatile("cp.async.cg.shared.global [%0], [%1], 16;" :: "r"(dst), "l"(src));
}
#define CP_COMMIT() asm volatile("cp.async.commit_group;" ::: "memory")
#define CP_WAIT0()  asm volatile("cp.async.wait_group 0;" ::: "memory")

// ---- kernel A: mask1 compaction (4 blocks) + g_vmean zeroing ----
__global__ void maskprep_kernel(const int* __restrict__ M1) {
    const int n = blockIdx.x, t = threadIdx.x;
    const int lane = t & 31, w = t >> 5;
    __shared__ int wsum[8], wexcl[8], s_cnt;

    g_vmean[n * 256 + t] = 0.f;

    int v[8], c = 0;
    #pragma unroll
    for (int i = 0; i < 8; i++) { v[i] = M1[n * LSEQ + t * 8 + i]; c += (v[i] != 0); }
    int inc = c;
    #pragma unroll
    for (int off = 1; off < 32; off <<= 1) {
        int x = __shfl_up_sync(0xffffffffu, inc, off);
        if (lane >= off) inc += x;
    }
    if (lane == 31) wsum[w] = inc;
    __syncthreads();
    if (t < 8) { int s = 0; for (int k2 = 0; k2 < t; k2++) s += wsum[k2]; wexcl[t] = s; }
    __syncthreads();
    int off = wexcl[w] + (inc - c);
    #pragma unroll
    for (int i = 0; i < 8; i++) if (v[i]) g_cidx[n][off++] = t * 8 + i;
    if (t == 0) { s_cnt = wexcl[7] + wsum[7]; g_cnt[n] = s_cnt; }
    __syncthreads();
    for (int idx = s_cnt + t; idx < LSEQ; idx += 256) g_cidx[n][idx] = 0;
}

// ---- kernel B: staging + fused vmean partials; grid (32 nh, 8 chunks) ----
__global__ void stage_kernel(const float* __restrict__ K, const float* __restrict__ V) {
    const int nh = blockIdx.x, n = nh >> 3, t = threadIdx.x;
    const int lane = t & 31, w = t >> 5;
    const int cbase = blockIdx.y * 256;
    const int* cidx = g_cidx[n];
    const int nvalid = g_cnt[n];
    const int nv64 = (nvalid + TKK - 1) & ~(TKK - 1);
    const float* kb = K + (size_t)nh * DH * LSEQ;
    const float* vb = V + (size_t)nh * DH * LSEQ;

    #pragma unroll
    for (int i = 0; i < 4; i++) {
        const int d = w + 8 * i;
        const float* row = vb + (size_t)d * LSEQ + cbase;
        float s0 = row[lane]       + row[lane + 32];
        float s1 = row[lane + 64]  + row[lane + 96];
        float s2 = row[lane + 128] + row[lane + 160];
        float s3 = row[lane + 192] + row[lane + 224];
        float s = (s0 + s1) + (s2 + s3);
        #pragma unroll
        for (int o = 16; o; o >>= 1) s += __shfl_xor_sync(0xffffffffu, s, o);
        if (lane == 0) atomicAdd(&g_vmean[nh * DH + d], s * (1.f / LSEQ));
    }

    if (cbase >= nv64) return;
    const int cend = min(cbase + 256, nv64);

    const int jk = cbase + t;
    if (jk < cend) {
        const bool ok = jk < nvalid;
        const int ci = ok ? cidx[jk] : 0;
        uint32_t b0[4], b1[4], b2[4], b3[4];
        #pragma unroll
        for (int q = 0; q < 4; q++) {
            b0[q] = ok ? packh(kb[(size_t)(2 * q)      * LSEQ + ci], kb[(size_t)(2 * q + 1)  * LSEQ + ci]) : 0u;
            b1[q] = ok ? packh(kb[(size_t)(2 * q + 8)  * LSEQ + ci], kb[(size_t)(2 * q + 9)  * LSEQ + ci]) : 0u;
            b2[q] = ok ? packh(kb[(size_t)(2 * q + 16) * LSEQ + ci], kb[(size_t)(2 * q + 17) * LSEQ + ci]) : 0u;
            b3[q] = ok ? packh(kb[(size_t)(2 * q + 24) * LSEQ + ci], kb[(size_t)(2 * q + 25) * LSEQ + ci]) : 0u;
        }
        uint4* dst = (uint4*)&g_Kc[nh][jk][0];
        dst[0] = make_uint4(b0[0], b0[1], b0[2], b0[3]);
        dst[1] = make_uint4(b1[0], b1[1], b1[2], b1[3]);
        dst[2] = make_uint4(b2[0], b2[1], b2[2], b2[3]);
        dst[3] = make_uint4(b3[0], b3[1], b3[2], b3[3]);
    }

    #pragma unroll
    for (int i = 0; i < 4; i++) {
        const int d = w + 8 * i;
        for (int jv = cbase + lane * 2; jv < cend; jv += 64) {
            const bool ok0 = jv < nvalid, ok1 = jv + 1 < nvalid;
            const int ci0 = ok0 ? cidx[jv] : 0, ci1 = ok1 ? cidx[jv + 1] : 0;
            *(uint32_t*)&g_Vc[nh][d][jv] =
                packh(ok0 ? vb[(size_t)d * LSEQ + ci0] : 0.f,
                      ok1 ? vb[(size_t)d * LSEQ + ci1] : 0.f);
        }
    }
}

// ---- kernel C: 4 warps x 32 rows, resident B-fragments, cp.async tiles ----
__global__ __launch_bounds__(128, 3) void attn_kernel(
    const float* __restrict__ Q, const int* __restrict__ M0,
    float* __restrict__ O)
{
    __shared__ __align__(16) unsigned short Ks[2][TKK * PK];
    __shared__ __align__(16) unsigned short Vh[2][DH * PVV];

    const int t = threadIdx.x, lane = t & 31, wid = t >> 5;
    const int g = lane >> 2, tq = lane & 3;
    const int nh = blockIdx.y, n = nh >> 3;
    const int l0 = blockIdx.x * TQ;
    const float scale2 = 1.4426950408889634f * 0.17677669529663687f;

    const float* qb = Q + (size_t)nh * DH * LSEQ;
    const int nvalid = g_cnt[n];
    const int ntiles = (nvalid + TKK - 1) / TKK;

    // cp.async addressing: 128 threads x 2 parts each side
    // K: 64 rows x 4 parts(16B);  V: 32 rows x 8 segs(16B)
    const int kp0 = 2 * t, kp1 = 2 * t + 1;
    const int kr0 = kp0 >> 2, kc0 = kp0 & 3, kr1 = kp1 >> 2, kc1 = kp1 & 3;
    const int vr0 = kp0 >> 3, vc0 = kp0 & 7, vr1 = kp1 >> 3, vc1 = kp1 & 7;
    const uint32_t ksb0 = smem_u32(Ks[0]), ksb1 = smem_u32(Ks[1]);
    const uint32_t vhb0 = smem_u32(Vh[0]), vhb1 = smem_u32(Vh[1]);
    const uint32_t kdst0[2] = {ksb0 + (uint32_t)(kr0 * PK + kc0 * 8) * 2,
                               ksb0 + (uint32_t)(kr1 * PK + kc1 * 8) * 2};
    const uint32_t kdst1[2] = {ksb1 + (uint32_t)(kr0 * PK + kc0 * 8) * 2,
                               ksb1 + (uint32_t)(kr1 * PK + kc1 * 8) * 2};
    const uint32_t vdst0[2] = {vhb0 + (uint32_t)(vr0 * PVV + vc0 * 8) * 2,
                               vhb0 + (uint32_t)(vr1 * PVV + vc1 * 8) * 2};
    const uint32_t vdst1[2] = {vhb1 + (uint32_t)(vr0 * PVV + vc0 * 8) * 2,
                               vhb1 + (uint32_t)(vr1 * PVV + vc1 * 8) * 2};

    // ---- issue tile 0 loads ----
    if (ntiles > 0) {
        cpasync16(kdst0[0], &g_Kc[nh][kr0][kc0 * 8]);
        cpasync16(kdst0[1], &g_Kc[nh][kr1][kc1 * 8]);
        cpasync16(vdst0[0], &g_Vc[nh][vr0][vc0 * 8]);
        cpasync16(vdst0[1], &g_Vc[nh][vr1][vc1 * 8]);
        CP_COMMIT();
    }

    // ---- Q fragments: warp owns rows l0 + wid*32 .. +31 (mt=2 halves) ----
    uint32_t qh[2][2][4];
    #pragma unroll
    for (int mt = 0; mt < 2; mt++) {
        const int r0 = l0 + wid * 32 + mt * 16 + g;
        #pragma unroll
        for (int kd = 0; kd < 2; kd++) {
            const int d0 = kd * 16 + 2 * tq;
            float xs[8];
            xs[0] = qb[(size_t)(d0)     * LSEQ + r0];
            xs[1] = qb[(size_t)(d0 + 1) * LSEQ + r0];
            xs[2] = qb[(size_t)(d0)     * LSEQ + r0 + 8];
            xs[3] = qb[(size_t)(d0 + 1) * LSEQ + r0 + 8];
            xs[4] = qb[(size_t)(d0 + 8) * LSEQ + r0];
            xs[5] = qb[(size_t)(d0 + 9) * LSEQ + r0];
            xs[6] = qb[(size_t)(d0 + 8) * LSEQ + r0 + 8];
            xs[7] = qb[(size_t)(d0 + 9) * LSEQ + r0 + 8];
            qh[mt][kd][0] = packh(xs[0], xs[1]); qh[mt][kd][1] = packh(xs[2], xs[3]);
            qh[mt][kd][2] = packh(xs[4], xs[5]); qh[mt][kd][3] = packh(xs[6], xs[7]);
        }
    }

    float o[2][4][4];
    #pragma unroll
    for (int mt = 0; mt < 2; mt++)
        #pragma unroll
        for (int nt = 0; nt < 4; nt++)
            #pragma unroll
            for (int i = 0; i < 4; i++) o[mt][nt][i] = 0.f;
    float lsacc[2][4] = {{0.f, 0.f, 0.f, 0.f}, {0.f, 0.f, 0.f, 0.f}};
    const uint32_t ones2 = 0x3C003C00u;
    uint32_t onesf[2] = {ones2, ones2};

    const int lrow = lane & 7;
    const int lblk = lane >> 3;

    if (ntiles > 0) { CP_WAIT0(); __syncthreads(); }

    for (int it = 0; it < ntiles; it++) {
        const int buf = it & 1;
        const bool more = (it + 1) < ntiles;

        // ---- issue cp.async for tile it+1 into the other buffer ----
        if (more) {
            const int base = (it + 1) * TKK;
            const uint32_t* kd = (buf == 0) ? kdst1 : kdst0;
            const uint32_t* vd = (buf == 0) ? vdst1 : vdst0;
            cpasync16(kd[0], &g_Kc[nh][base + kr0][kc0 * 8]);
            cpasync16(kd[1], &g_Kc[nh][base + kr1][kc1 * 8]);
            cpasync16(vd[0], &g_Vc[nh][vr0][base + vc0 * 8]);
            cpasync16(vd[1], &g_Vc[nh][vr1][base + vc1 * 8]);
            CP_COMMIT();
        }

        const uint32_t ksb = (buf == 0) ? ksb0 : ksb1;
        const uint32_t vhb = (buf == 0) ? vhb0 : vhb1;

        // ---- load ALL B-fragments once (resident) ----
        uint32_t bhAll[8][4];
        #pragma unroll
        for (int nt = 0; nt < 8; nt++)
            ldmx4(bhAll[nt], ksb + (uint32_t)(((nt * 8 + lrow) * PK + lblk * 8) * 2));
        uint32_t vfAll[4][8];
        #pragma unroll
        for (int ntv = 0; ntv < 4; ntv++) {
            const uint32_t rvb = vhb + (uint32_t)(((ntv * 8 + lrow) * PVV + lblk * 8) * 2);
            ldmx4(vfAll[ntv], rvb);
            ldmx4(vfAll[ntv] + 4, rvb + 64);
        }

        const int lim = min(nvalid - it * TKK, TKK);
        const bool full = (lim == TKK);

        // ---- per-mt streamed: QK -> exp -> ph -> ls/PV MMAs ----
        #pragma unroll
        for (int mt = 0; mt < 2; mt++) {
            #pragma unroll
            for (int j = 0; j < 4; j++) {
                float sa[4] = {0.f, 0.f, 0.f, 0.f};
                float sb[4] = {0.f, 0.f, 0.f, 0.f};
                mma16816(sa, qh[mt][0], bhAll[2 * j]);
                mma16816(sa, qh[mt][1], bhAll[2 * j] + 2);
                mma16816(sb, qh[mt][0], bhAll[2 * j + 1]);
                mma16816(sb, qh[mt][1], bhAll[2 * j + 1] + 2);

                const int ca = 16 * j + 2 * tq;       // nt = 2j
                const int cb = ca + 8;                // nt = 2j+1
                float p0 = ex2f(sa[0] * scale2);
                float p1 = ex2f(sa[1] * scale2);
                float p2 = ex2f(sa[2] * scale2);
                float p3 = ex2f(sa[3] * scale2);
                float p4 = ex2f(sb[0] * scale2);
                float p5 = ex2f(sb[1] * scale2);
                float p6 = ex2f(sb[2] * scale2);
                float p7 = ex2f(sb[3] * scale2);
                if (!full) {
                    if (ca >= lim)     { p0 = 0.f; p2 = 0.f; }
                    if (ca + 1 >= lim) { p1 = 0.f; p3 = 0.f; }
                    if (cb >= lim)     { p4 = 0.f; p6 = 0.f; }
                    if (cb + 1 >= lim) { p5 = 0.f; p7 = 0.f; }
                }
                uint32_t ph[4];
                ph[0] = packh(p0, p1);
                ph[1] = packh(p2, p3);
                ph[2] = packh(p4, p5);
                ph[3] = packh(p6, p7);

                mma16816(lsacc[mt], ph, onesf);
                #pragma unroll
                for (int ntv = 0; ntv < 4; ntv++)
                    mma16816(o[mt][ntv], ph, &vfAll[ntv][2 * j]);
            }
        }

        if (more) { CP_WAIT0(); __syncthreads(); }
    }

    // ---- epilogue ----
    float* ob = O + (size_t)nh * DH * LSEQ;
    #pragma unroll
    for (int mt = 0; mt < 2; mt++) {
        const int r0 = l0 + wid * 32 + mt * 16 + g;
        const int rv0 = M0[n * LSEQ + r0];
        const int rv1 = M0[n * LSEQ + r0 + 8];
        const bool mean0 = (rv0 == 0) || (nvalid == 0);
        const bool mean1 = (rv1 == 0) || (nvalid == 0);
        const float inv0 = (lsacc[mt][0] > 0.f) ? 1.f / lsacc[mt][0] : 0.f;
        const float inv1 = (lsacc[mt][2] > 0.f) ? 1.f / lsacc[mt][2] : 0.f;
        #pragma unroll
        for (int ntv = 0; ntv < 4; ntv++) {
            const int d0 = ntv * 8 + 2 * tq;
            const float mv0 = g_vmean[nh * DH + d0];
            const float mv1 = g_vmean[nh * DH + d0 + 1];
            ob[(size_t)d0       * LSEQ + r0]     = mean0 ? mv0 : o[mt][ntv][0] * inv0;
            ob[(size_t)(d0 + 1) * LSEQ + r0]     = mean0 ? mv1 : o[mt][ntv][1] * inv0;
            ob[(size_t)d0       * LSEQ + r0 + 8] = mean1 ? mv0 : o[mt][ntv][2] * inv1;
            ob[(size_t)(d0 + 1) * LSEQ + r0 + 8] = mean1 ? mv1 : o[mt][ntv][3] * inv1;
        }
    }
}

extern "C" void kernel_launch(void* const* d_in, const int* in_sizes, int n_in,
                              void* d_out, int out_size)
{
    const float* q  = (const float*)d_in[0];
    const float* k  = (const float*)d_in[1];
    const float* v  = (const float*)d_in[2];
    const int*   m0 = (const int*)d_in[3];
    const int*   m1 = (const int*)d_in[4];
    float* out = (float*)d_out;

    maskprep_kernel<<<NB, 256>>>(m1);
    stage_kernel<<<dim3(NH_TOT, 8), 256>>>(k, v);
    dim3 grid(LSEQ / TQ, NH_TOT);   // 16 x 32 = 512 blocks
    attn_kernel<<<grid, 128>>>(q, m0, out);
}